// round 8
// baseline (speedup 1.0000x reference)
#include <cuda_runtime.h>
#include <cstdint>
#include <cstddef>

// Problem constants
static const int B  = 512;
static const int S  = 100;
static const int E  = 256;
static const int H  = 256;
static const int G4 = 1024;   // 4*H

#define TINYF 1.17549435e-38f

// ---------------- scratch (device globals; no allocations allowed) ----------------
__device__ float d_embedded[512 * 100 * 256];          // [b][s][e]
__device__ float d_xih[512 * 100 * 1024];              // [b][s][4H] (encoder input proj + biases)
__device__ float d_enc [512 * 100 * 256];              // [b][s][h]
__device__ float d_refg[512 * 100 * 256];              // [b][s][h]
__device__ float d_refp[512 * 100 * 256];              // [b][s][h]
__device__ float d_h[512 * 256];                       // encoder final h
__device__ float d_c[512 * 256];                       // encoder final c
__device__ float d_gum[100 * 512 * 100];               // gumbel noise per (t,b,s)

// ---------------- helpers ----------------
__device__ __forceinline__ float sigf(float x) { return 1.0f / (1.0f + expf(-x)); }
__device__ __forceinline__ float neg_inf() { return __int_as_float((int)0xff800000); }

// Threefry-2x32, 20 rounds (matches JAX threefry2x32_p)
__device__ __forceinline__ void threefry2x32(uint32_t k0, uint32_t k1,
                                             uint32_t x0, uint32_t x1,
                                             uint32_t* o0, uint32_t* o1)
{
    uint32_t ks2 = k0 ^ k1 ^ 0x1BD11BDAu;
#define TFR(r) { x0 += x1; x1 = (x1 << (r)) | (x1 >> (32 - (r))); x1 ^= x0; }
    x0 += k0;  x1 += k1;
    TFR(13) TFR(15) TFR(26) TFR(6)
    x0 += k1;  x1 += ks2 + 1u;
    TFR(17) TFR(29) TFR(16) TFR(24)
    x0 += ks2; x1 += k0 + 2u;
    TFR(13) TFR(15) TFR(26) TFR(6)
    x0 += k0;  x1 += k1 + 3u;
    TFR(17) TFR(29) TFR(16) TFR(24)
    x0 += k1;  x1 += ks2 + 4u;
    TFR(13) TFR(15) TFR(26) TFR(6)
    x0 += ks2; x1 += k0 + 5u;
#undef TFR
    *o0 = x0; *o1 = x1;
}

// ---------------- embedding ----------------
__global__ void embedk(const float* __restrict__ inp, const float* __restrict__ emb)
{
    int i = blockIdx.x * blockDim.x + threadIdx.x;
    if (i >= B * S * E) return;
    int e  = i % E;
    int bs = i / E;
    int b  = bs / S;
    int s  = bs % S;
    float a0 = inp[(b * 2 + 0) * S + s];
    float a1 = inp[(b * 2 + 1) * S + s];
    d_embedded[i] = fmaf(a1, emb[E + e], a0 * emb[e]);
}

// ---------------- gumbel noise (keys computed inline) ----------------
// key_t = threefry((0,1),(0,t)) ; bits[n] = v0^v1 of threefry(key_t,(0,n)), n=b*S+s
__global__ void gumbelk()
{
    int i = blockIdx.x * blockDim.x + threadIdx.x;
    if (i >= S * B * S) return;
    int step   = i / (B * S);
    uint32_t n = (uint32_t)(i - step * (B * S));
    uint32_t k0, k1;
    threefry2x32(0u, 1u, 0u, (uint32_t)step, &k0, &k1);
    uint32_t a, bb;
    threefry2x32(k0, k1, 0u, n, &a, &bb);
    uint32_t bits = a ^ bb;
    float f = __uint_as_float((bits >> 9) | 0x3f800000u) - 1.0f;
    float u = fmaxf(TINYF, f + TINYF);
    d_gum[i] = -logf(-logf(u));
}

// ---------------- generic tiled SGEMM:  C[M,N] = A[M,K] @ W[N,K]^T (+b1)(+b2) -------
// 64x64 tile, 256 threads, 4x4 microtile.  M,N multiples of 64; K multiple of 16.
// (kept bit-identical to the round-5 version, which validated)
__global__ void __launch_bounds__(256)
sgemm64(const float* __restrict__ A, int lda,
        const float* __restrict__ Wm, int K,
        const float* __restrict__ b1,
        const float* __restrict__ b2,
        float* __restrict__ C, int ldc)
{
    __shared__ float As[64][17];
    __shared__ float Ws[64][17];
    const int bm = blockIdx.y * 64, bn = blockIdx.x * 64;
    const int tid = threadIdx.x;
    const int tx = tid & 15, ty = tid >> 4;
    float acc[4][4];
#pragma unroll
    for (int i = 0; i < 4; i++)
#pragma unroll
        for (int j = 0; j < 4; j++) acc[i][j] = 0.0f;

    for (int k0 = 0; k0 < K; k0 += 16) {
#pragma unroll
        for (int r = 0; r < 4; r++) {
            int m = ty + 16 * r;
            As[m][tx] = A [(size_t)(bm + m) * lda + k0 + tx];
            Ws[m][tx] = Wm[(size_t)(bn + m) * K   + k0 + tx];
        }
        __syncthreads();
#pragma unroll
        for (int k = 0; k < 16; k++) {
            float a0 = As[ty * 4 + 0][k], a1 = As[ty * 4 + 1][k];
            float a2 = As[ty * 4 + 2][k], a3 = As[ty * 4 + 3][k];
            float w0 = Ws[tx * 4 + 0][k], w1 = Ws[tx * 4 + 1][k];
            float w2 = Ws[tx * 4 + 2][k], w3 = Ws[tx * 4 + 3][k];
            acc[0][0] = fmaf(a0, w0, acc[0][0]); acc[0][1] = fmaf(a0, w1, acc[0][1]);
            acc[0][2] = fmaf(a0, w2, acc[0][2]); acc[0][3] = fmaf(a0, w3, acc[0][3]);
            acc[1][0] = fmaf(a1, w0, acc[1][0]); acc[1][1] = fmaf(a1, w1, acc[1][1]);
            acc[1][2] = fmaf(a1, w2, acc[1][2]); acc[1][3] = fmaf(a1, w3, acc[1][3]);
            acc[2][0] = fmaf(a2, w0, acc[2][0]); acc[2][1] = fmaf(a2, w1, acc[2][1]);
            acc[2][2] = fmaf(a2, w2, acc[2][2]); acc[2][3] = fmaf(a2, w3, acc[2][3]);
            acc[3][0] = fmaf(a3, w0, acc[3][0]); acc[3][1] = fmaf(a3, w1, acc[3][1]);
            acc[3][2] = fmaf(a3, w2, acc[3][2]); acc[3][3] = fmaf(a3, w3, acc[3][3]);
        }
        __syncthreads();
    }
#pragma unroll
    for (int i = 0; i < 4; i++)
#pragma unroll
        for (int j = 0; j < 4; j++) {
            int row = bm + ty * 4 + i, col = bn + tx * 4 + j;
            float v = acc[i][j];
            if (b1) v += b1[col];
            if (b2) v += b2[col];
            C[(size_t)row * ldc + col] = v;
        }
}

// ---------------- persistent encoder: 4 batch rows per block, full 100-step scan ----
// thread t owns hidden unit hh=t for 4 rows; gates columns j = t + 256*g.
__global__ void __launch_bounds__(256)
encoderk(const float* __restrict__ Whh)
{
    const int tid = threadIdx.x;
    const int b0  = blockIdx.x * 4;
    __shared__ __align__(16) float hs[4][256];
    float creg[4];
#pragma unroll
    for (int r = 0; r < 4; r++) { hs[r][tid] = 0.0f; creg[r] = 0.0f; }
    __syncthreads();

    for (int s = 0; s < S; s++) {
        float acc[4][4];
#pragma unroll
        for (int g = 0; g < 4; g++)
#pragma unroll
            for (int r = 0; r < 4; r++) acc[g][r] = 0.0f;

#pragma unroll 2
        for (int kg = 0; kg < 64; kg++) {
            int k = kg * 4;
            float4 xv[4];
#pragma unroll
            for (int r = 0; r < 4; r++) xv[r] = *(const float4*)&hs[r][k];
#pragma unroll
            for (int g = 0; g < 4; g++) {
                float4 w = *(const float4*)&Whh[(size_t)(tid + 256 * g) * 256 + k];
#pragma unroll
                for (int r = 0; r < 4; r++) {
                    acc[g][r] = fmaf(w.x, xv[r].x, acc[g][r]);
                    acc[g][r] = fmaf(w.y, xv[r].y, acc[g][r]);
                    acc[g][r] = fmaf(w.z, xv[r].z, acc[g][r]);
                    acc[g][r] = fmaf(w.w, xv[r].w, acc[g][r]);
                }
            }
        }
        // gates = (h@Whh^T) + xih  (xih already has Wih-proj + both biases; same order as R5)
#pragma unroll
        for (int g = 0; g < 4; g++)
#pragma unroll
            for (int r = 0; r < 4; r++)
                acc[g][r] += d_xih[((size_t)(b0 + r) * S + s) * G4 + tid + 256 * g];

        __syncthreads();
#pragma unroll
        for (int r = 0; r < 4; r++) {
            float ig = sigf(acc[0][r]);
            float fg = sigf(acc[1][r]);
            float gg = tanhf(acc[2][r]);
            float og = sigf(acc[3][r]);
            float c  = fg * creg[r] + ig * gg;
            creg[r]  = c;
            float h  = og * tanhf(c);
            hs[r][tid] = h;
            d_enc[((size_t)(b0 + r) * S + s) * H + tid] = h;
        }
        __syncthreads();
    }
#pragma unroll
    for (int r = 0; r < 4; r++) {
        d_h[(size_t)(b0 + r) * H + tid] = hs[r][tid];
        d_c[(size_t)(b0 + r) * H + tid] = creg[r];
    }
}

// ---------------- persistent decoder: 4 batch rows per block, full 100-step scan ----
__global__ void __launch_bounds__(256)
decoderk(const float* __restrict__ Wih, const float* __restrict__ Whh,
         const float* __restrict__ bih, const float* __restrict__ bhh,
         const float* __restrict__ gWq, const float* __restrict__ gbq,
         const float* __restrict__ gV,
         const float* __restrict__ pWq, const float* __restrict__ pbq,
         const float* __restrict__ pV,
         const float* __restrict__ start,
         float* __restrict__ out_probs, float* __restrict__ out_idx)
{
    const int tid  = threadIdx.x;
    const int lane = tid & 31;
    const int w    = tid >> 5;
    const int b0   = blockIdx.x * 4;

    __shared__ __align__(16) float xs[4][512];   // [dec_in(256) | h(256)]
    __shared__ __align__(16) float cs[4][256];
    __shared__ __align__(16) float qs[4][256];   // qq, then reused for q (readout)
    __shared__ __align__(16) float qp[4][256];
    __shared__ float lgm[4][100];                // glimpse logits, then pointer logits
    __shared__ float pr [4][100];                // glimpse softmax probs
    __shared__ unsigned char msk[4][104];
    __shared__ int sidx[4];

    // per-thread bias (hoisted; applied as (acc+bih)+bhh, matching R5 epilogue order)
    float bi1[4], bi2[4];
#pragma unroll
    for (int g = 0; g < 4; g++) { bi1[g] = bih[tid + 256 * g]; bi2[g] = bhh[tid + 256 * g]; }
    const float gbq_t = gbq[tid];
    const float pbq_t = pbq[tid];

#pragma unroll
    for (int r = 0; r < 4; r++) {
        xs[r][tid]       = start[tid];
        xs[r][256 + tid] = d_h[(size_t)(b0 + r) * H + tid];
        cs[r][tid]       = d_c[(size_t)(b0 + r) * H + tid];
    }
    for (int i = tid; i < 4 * 100; i += 256) msk[i / 100][i % 100] = 0;
    __syncthreads();

    for (int t = 0; t < S; t++) {
        // ---- LSTM gates: x=[dec_in|h], W=[Wih|Whh], ascending k (matches R5) ----
        float acc[4][4];
#pragma unroll
        for (int g = 0; g < 4; g++)
#pragma unroll
            for (int r = 0; r < 4; r++) acc[g][r] = 0.0f;

#pragma unroll 2
        for (int kg = 0; kg < 64; kg++) {
            int k = kg * 4;
            float4 xv[4];
#pragma unroll
            for (int r = 0; r < 4; r++) xv[r] = *(const float4*)&xs[r][k];
#pragma unroll
            for (int g = 0; g < 4; g++) {
                float4 wv = *(const float4*)&Wih[(size_t)(tid + 256 * g) * 256 + k];
#pragma unroll
                for (int r = 0; r < 4; r++) {
                    acc[g][r] = fmaf(wv.x, xv[r].x, acc[g][r]);
                    acc[g][r] = fmaf(wv.y, xv[r].y, acc[g][r]);
                    acc[g][r] = fmaf(wv.z, xv[r].z, acc[g][r]);
                    acc[g][r] = fmaf(wv.w, xv[r].w, acc[g][r]);
                }
            }
        }
#pragma unroll 2
        for (int kg = 0; kg < 64; kg++) {
            int k = kg * 4;
            float4 xv[4];
#pragma unroll
            for (int r = 0; r < 4; r++) xv[r] = *(const float4*)&xs[r][256 + k];
#pragma unroll
            for (int g = 0; g < 4; g++) {
                float4 wv = *(const float4*)&Whh[(size_t)(tid + 256 * g) * 256 + k];
#pragma unroll
                for (int r = 0; r < 4; r++) {
                    acc[g][r] = fmaf(wv.x, xv[r].x, acc[g][r]);
                    acc[g][r] = fmaf(wv.y, xv[r].y, acc[g][r]);
                    acc[g][r] = fmaf(wv.z, xv[r].z, acc[g][r]);
                    acc[g][r] = fmaf(wv.w, xv[r].w, acc[g][r]);
                }
            }
        }
        __syncthreads();
        // ---- LSTM cell for hh=tid, all 4 rows (gates live in registers) ----
#pragma unroll
        for (int r = 0; r < 4; r++) {
            float ig = sigf((acc[0][r] + bi1[0]) + bi2[0]);
            float fg = sigf((acc[1][r] + bi1[1]) + bi2[1]);
            float gg = tanhf((acc[2][r] + bi1[2]) + bi2[2]);
            float og = sigf((acc[3][r] + bi1[3]) + bi2[3]);
            float c  = fg * cs[r][tid] + ig * gg;
            cs[r][tid] = c;
            xs[r][256 + tid] = og * tanhf(c);
        }
        __syncthreads();

        // ---- qq = h@gWq^T + gbq ----
        {
            float a[4] = {0.f, 0.f, 0.f, 0.f};
#pragma unroll 2
            for (int kg = 0; kg < 64; kg++) {
                int k = kg * 4;
                float4 wv = *(const float4*)&gWq[(size_t)tid * 256 + k];
#pragma unroll
                for (int r = 0; r < 4; r++) {
                    float4 hv = *(const float4*)&xs[r][256 + k];
                    a[r] = fmaf(wv.x, hv.x, a[r]);
                    a[r] = fmaf(wv.y, hv.y, a[r]);
                    a[r] = fmaf(wv.z, hv.z, a[r]);
                    a[r] = fmaf(wv.w, hv.w, a[r]);
                }
            }
#pragma unroll
            for (int r = 0; r < 4; r++) qs[r][tid] = a[r] + gbq_t;
        }
        __syncthreads();

        // ---- glimpse logits lg[r][s] (warp w: row w>>1, s-half (w&1)*50) ----
        {
            int r  = w >> 1;
            int s0 = (w & 1) * 50;
            float qv[8], vv[8];
#pragma unroll
            for (int k = 0; k < 8; k++) {
                int hh = k * 32 + lane;
                qv[k] = qs[r][hh];
                vv[k] = gV[hh];
            }
            for (int si = 0; si < 50; si++) {
                int s = s0 + si;
                const float* rp = &d_refg[(((size_t)(b0 + r)) * S + s) * H];
                float sum = 0.0f;
#pragma unroll
                for (int k = 0; k < 8; k++) {
                    int hh = k * 32 + lane;
                    sum = fmaf(vv[k], tanhf(qv[k] + __ldg(&rp[hh])), sum);
                }
#pragma unroll
                for (int o = 16; o > 0; o >>= 1) sum += __shfl_xor_sync(0xffffffffu, sum, o);
                if (lane == 0) lgm[r][s] = msk[r][s] ? neg_inf() : sum;
            }
        }
        __syncthreads();

        // ---- glimpse softmax -> pr (sum order replicates R5's binary tree) ----
        if (w < 4) {
            int r = w;
            float v[4];
#pragma unroll
            for (int j = 0; j < 4; j++) {
                int s = lane + 32 * j;
                v[j] = (s < 100) ? lgm[r][s] : neg_inf();
            }
            float m = fmaxf(fmaxf(v[0], v[1]), fmaxf(v[2], v[3]));
#pragma unroll
            for (int o = 16; o > 0; o >>= 1) m = fmaxf(m, __shfl_xor_sync(0xffffffffu, m, o));
            float e[4];
#pragma unroll
            for (int j = 0; j < 4; j++) {
                int s = lane + 32 * j;
                e[j] = (s < 100) ? expf(v[j] - m) : 0.0f;
            }
            float sum = (e[0] + e[2]) + (e[1] + e[3]);   // R5 tree nesting
#pragma unroll
            for (int o = 16; o > 0; o >>= 1) sum += __shfl_xor_sync(0xffffffffu, sum, o);
#pragma unroll
            for (int j = 0; j < 4; j++) {
                int s = lane + 32 * j;
                if (s < 100) pr[r][s] = e[j] / sum;
            }
        }
        __syncthreads();

        // ---- readout: q[r][tid] = sum_s pr[r][s]*enc[b][s][tid] (ascending s) ----
        {
            float a[4] = {0.f, 0.f, 0.f, 0.f};
            for (int s = 0; s < S; s++) {
#pragma unroll
                for (int r = 0; r < 4; r++)
                    a[r] = fmaf(pr[r][s],
                                __ldg(&d_enc[(((size_t)(b0 + r)) * S + s) * H + tid]),
                                a[r]);
            }
#pragma unroll
            for (int r = 0; r < 4; r++) qs[r][tid] = a[r];
        }
        __syncthreads();

        // ---- qp = q@pWq^T + pbq ----
        {
            float a[4] = {0.f, 0.f, 0.f, 0.f};
#pragma unroll 2
            for (int kg = 0; kg < 64; kg++) {
                int k = kg * 4;
                float4 wv = *(const float4*)&pWq[(size_t)tid * 256 + k];
#pragma unroll
                for (int r = 0; r < 4; r++) {
                    float4 hv = *(const float4*)&qs[r][k];
                    a[r] = fmaf(wv.x, hv.x, a[r]);
                    a[r] = fmaf(wv.y, hv.y, a[r]);
                    a[r] = fmaf(wv.z, hv.z, a[r]);
                    a[r] = fmaf(wv.w, hv.w, a[r]);
                }
            }
#pragma unroll
            for (int r = 0; r < 4; r++) qp[r][tid] = a[r] + pbq_t;
        }
        __syncthreads();

        // ---- pointer logits lp[r][s] = mask ? -inf : 10*tanh(V·tanh(qp+refp)) ----
        {
            int r  = w >> 1;
            int s0 = (w & 1) * 50;
            float qv[8], vv[8];
#pragma unroll
            for (int k = 0; k < 8; k++) {
                int hh = k * 32 + lane;
                qv[k] = qp[r][hh];
                vv[k] = pV[hh];
            }
            for (int si = 0; si < 50; si++) {
                int s = s0 + si;
                const float* rp = &d_refp[(((size_t)(b0 + r)) * S + s) * H];
                float sum = 0.0f;
#pragma unroll
                for (int k = 0; k < 8; k++) {
                    int hh = k * 32 + lane;
                    sum = fmaf(vv[k], tanhf(qv[k] + __ldg(&rp[hh])), sum);
                }
#pragma unroll
                for (int o = 16; o > 0; o >>= 1) sum += __shfl_xor_sync(0xffffffffu, sum, o);
                if (lane == 0) lgm[r][s] = msk[r][s] ? neg_inf() : (10.0f * tanhf(sum));
            }
        }
        __syncthreads();

        // ---- sample: argmax(lp+gumbel), probs=softmax(lp), mask & dec_in update ----
        if (w < 4) {
            int r = w;
            int b = b0 + r;
            float v[4];
#pragma unroll
            for (int j = 0; j < 4; j++) {
                int s = lane + 32 * j;
                v[j] = (s < 100) ? lgm[r][s] : neg_inf();
            }
            // argmax over lp+gumbel with first-index tie-break (exact comparisons)
            float bv = neg_inf(); int bi = 0;
#pragma unroll
            for (int j = 0; j < 4; j++) {
                int s = lane + 32 * j;
                if (s < 100) {
                    float y = v[j] + d_gum[((size_t)t * B + b) * S + s];
                    if (y > bv) { bv = y; bi = s; }
                }
            }
#pragma unroll
            for (int o = 16; o > 0; o >>= 1) {
                float vo = __shfl_xor_sync(0xffffffffu, bv, o);
                int   io = __shfl_xor_sync(0xffffffffu, bi, o);
                if (vo > bv || (vo == bv && io < bi)) { bv = vo; bi = io; }
            }
            // softmax(lp) (R5 tree nesting)
            float m = fmaxf(fmaxf(v[0], v[1]), fmaxf(v[2], v[3]));
#pragma unroll
            for (int o = 16; o > 0; o >>= 1) m = fmaxf(m, __shfl_xor_sync(0xffffffffu, m, o));
            float e[4];
#pragma unroll
            for (int j = 0; j < 4; j++) {
                int s = lane + 32 * j;
                e[j] = (s < 100) ? expf(v[j] - m) : 0.0f;
            }
            float sum = (e[0] + e[2]) + (e[1] + e[3]);
#pragma unroll
            for (int o = 16; o > 0; o >>= 1) sum += __shfl_xor_sync(0xffffffffu, sum, o);
#pragma unroll
            for (int j = 0; j < 4; j++) {
                int s = lane + 32 * j;
                if (s < 100) out_probs[((size_t)t * B + b) * S + s] = e[j] / sum;
            }
            if (lane == 0) {
                sidx[r] = bi;
                msk[r][bi] = 1;
                out_idx[(size_t)t * B + b] = (float)bi;
            }
        }
        __syncthreads();
        // dec_in <- embedded[b][idx]
#pragma unroll
        for (int r = 0; r < 4; r++)
            xs[r][tid] = d_embedded[(((size_t)(b0 + r)) * S + sidx[r]) * E + tid];
        __syncthreads();
    }
}

// ---------------- host ----------------
extern "C" void kernel_launch(void* const* d_in, const int* in_sizes, int n_in,
                              void* d_out, int out_size)
{
    (void)in_sizes; (void)n_in; (void)out_size;
    const float* inputs  = (const float*)d_in[0];
    const float* emb     = (const float*)d_in[1];
    const float* enc_Wih = (const float*)d_in[2];
    const float* enc_Whh = (const float*)d_in[3];
    const float* enc_bih = (const float*)d_in[4];
    const float* enc_bhh = (const float*)d_in[5];
    const float* dec_Wih = (const float*)d_in[6];
    const float* dec_Whh = (const float*)d_in[7];
    const float* dec_bih = (const float*)d_in[8];
    const float* dec_bhh = (const float*)d_in[9];
    const float* g_Wq    = (const float*)d_in[10];
    const float* g_bq    = (const float*)d_in[11];
    const float* g_Wr    = (const float*)d_in[12];
    const float* g_br    = (const float*)d_in[13];
    const float* g_V     = (const float*)d_in[14];
    const float* p_Wq    = (const float*)d_in[15];
    const float* p_bq    = (const float*)d_in[16];
    const float* p_Wr    = (const float*)d_in[17];
    const float* p_br    = (const float*)d_in[18];
    const float* p_V     = (const float*)d_in[19];
    const float* start   = (const float*)d_in[20];

    float* out       = (float*)d_out;
    float* out_probs = out;                              // [S,B,S]
    float* out_idx   = out + (size_t)S * B * S;          // [S,B] (as float)

    float *p_embp, *p_xih, *p_enc, *p_refg, *p_refp;
    cudaGetSymbolAddress((void**)&p_embp, d_embedded);
    cudaGetSymbolAddress((void**)&p_xih,  d_xih);
    cudaGetSymbolAddress((void**)&p_enc,  d_enc);
    cudaGetSymbolAddress((void**)&p_refg, d_refg);
    cudaGetSymbolAddress((void**)&p_refp, d_refp);

    // ---- prologue (3 small kernels + 1 big GEMM) ----
    embedk <<<(B * S * E + 255) / 256, 256>>>(inputs, emb);
    gumbelk<<<(S * B * S + 255) / 256, 256>>>();

    // Xih[b][s][:] = embedded[b][s]@enc_Wih^T + bih + bhh   (M=51200, N=1024, K=256)
    sgemm64<<<dim3(G4 / 64, (B * S) / 64), 256>>>(p_embp, E, enc_Wih, E,
                                                  enc_bih, enc_bhh, p_xih, G4);

    // ---- persistent encoder scan (one kernel, 100 steps inside) ----
    encoderk<<<B / 4, 256>>>(enc_Whh);

    // ---- ref projections (conv1d k=1) ----
    sgemm64<<<dim3(H / 64, (B * S) / 64), 256>>>(p_enc, H, g_Wr, H, g_br, nullptr, p_refg, H);
    sgemm64<<<dim3(H / 64, (B * S) / 64), 256>>>(p_enc, H, p_Wr, H, p_br, nullptr, p_refp, H);

    // ---- persistent decoder scan (one kernel, 100 steps inside) ----
    decoderk<<<B / 4, 256>>>(dec_Wih, dec_Whh, dec_bih, dec_bhh,
                             g_Wq, g_bq, g_V, p_Wq, p_bq, p_V,
                             start, out_probs, out_idx);
}

// round 10
// speedup vs baseline: 1.5024x; 1.5024x over previous
#include <cuda_runtime.h>
#include <cstdint>
#include <cstddef>

// Problem constants
static const int B  = 512;
static const int S  = 100;
static const int E  = 256;
static const int H  = 256;

#define TINYF 1.17549435e-38f

// ---------------- scratch (device globals; no allocations allowed) ----------------
__device__ float d_enc [512 * 100 * 256];              // [b][s][h]
__device__ float d_refg[512 * 100 * 256];              // [b][s][h]
__device__ float d_refp[512 * 100 * 256];              // [b][s][h]
__device__ float d_h[512 * 256];                       // encoder final h
__device__ float d_c[512 * 256];                       // encoder final c
__device__ float d_gum[100 * 512 * 100];               // gumbel noise per (t,b,s)
__device__ float d_Menc[2 * 1024];                     // emb @ enc_Wih^T   (rank-2 factor)
__device__ float d_Mdec[2 * 1024];                     // emb @ dec_Wih^T
__device__ float d_xstart[1024];                       // start @ dec_Wih^T

// ---------------- helpers ----------------
__device__ __forceinline__ float sigf(float x) { return 1.0f / (1.0f + expf(-x)); }
__device__ __forceinline__ float neg_inf() { return __int_as_float((int)0xff800000); }

// Threefry-2x32, 20 rounds (matches JAX threefry2x32_p)
__device__ __forceinline__ void threefry2x32(uint32_t k0, uint32_t k1,
                                             uint32_t x0, uint32_t x1,
                                             uint32_t* o0, uint32_t* o1)
{
    uint32_t ks2 = k0 ^ k1 ^ 0x1BD11BDAu;
#define TFR(r) { x0 += x1; x1 = (x1 << (r)) | (x1 >> (32 - (r))); x1 ^= x0; }
    x0 += k0;  x1 += k1;
    TFR(13) TFR(15) TFR(26) TFR(6)
    x0 += k1;  x1 += ks2 + 1u;
    TFR(17) TFR(29) TFR(16) TFR(24)
    x0 += ks2; x1 += k0 + 2u;
    TFR(13) TFR(15) TFR(26) TFR(6)
    x0 += k0;  x1 += k1 + 3u;
    TFR(17) TFR(29) TFR(16) TFR(24)
    x0 += k1;  x1 += ks2 + 4u;
    TFR(13) TFR(15) TFR(26) TFR(6)
    x0 += ks2; x1 += k0 + 5u;
#undef TFR
    *o0 = x0; *o1 = x1;
}

// ---------------- gumbel noise ----------------
__global__ void gumbelk()
{
    int i = blockIdx.x * blockDim.x + threadIdx.x;
    if (i >= S * B * S) return;
    int step   = i / (B * S);
    uint32_t n = (uint32_t)(i - step * (B * S));
    uint32_t k0, k1;
    threefry2x32(0u, 1u, 0u, (uint32_t)step, &k0, &k1);
    uint32_t a, bb;
    threefry2x32(k0, k1, 0u, n, &a, &bb);
    uint32_t bits = a ^ bb;
    float f = __uint_as_float((bits >> 9) | 0x3f800000u) - 1.0f;
    float u = fmaxf(TINYF, f + TINYF);
    d_gum[i] = -logf(-logf(u));
}

// ---------------- tiny precompute: rank-2 factors + start projection ----------------
__global__ void precompk(const float* __restrict__ emb,
                         const float* __restrict__ enc_Wih,
                         const float* __restrict__ dec_Wih,
                         const float* __restrict__ start)
{
    int j = blockIdx.x * blockDim.x + threadIdx.x;
    if (j >= 1024) return;
    float m0 = 0.f, m1 = 0.f, n0 = 0.f, n1 = 0.f, xs = 0.f;
    for (int e = 0; e < 256; e++) {
        float we = enc_Wih[(size_t)j * 256 + e];
        float wd = dec_Wih[(size_t)j * 256 + e];
        m0 = fmaf(emb[e],       we, m0);
        m1 = fmaf(emb[256 + e], we, m1);
        n0 = fmaf(emb[e],       wd, n0);
        n1 = fmaf(emb[256 + e], wd, n1);
        xs = fmaf(start[e],     wd, xs);
    }
    d_Menc[j] = m0; d_Menc[1024 + j] = m1;
    d_Mdec[j] = n0; d_Mdec[1024 + j] = n1;
    d_xstart[j] = xs;
}

// ---------------- persistent encoder + fused ref projections --------------------
// 128 blocks x 512 threads. 4 batch rows/block. thread = (hh = tid&255, half = tid>>8).
// K dimension split across halves; reduction via shared red[][].
__global__ void __launch_bounds__(512)
encoderk(const float* __restrict__ inputs,
         const float* __restrict__ Whh,
         const float* __restrict__ bih, const float* __restrict__ bhh,
         const float* __restrict__ gWr, const float* __restrict__ gbr,
         const float* __restrict__ pWr, const float* __restrict__ pbr)
{
    const int tid  = threadIdx.x;
    const int hh   = tid & 255;
    const int half = tid >> 8;
    const int k0   = half * 128;
    const int b0   = blockIdx.x * 4;

    __shared__ __align__(16) float hs[4][256];
    __shared__ __align__(16) float red[16][256];

    float creg[4] = {0.f, 0.f, 0.f, 0.f};
    for (int i = tid; i < 1024; i += 512) ((float*)hs)[i] = 0.0f;

    // hoisted per-thread constants (used by half 0 in the epilogues)
    float me0[4], me1[4], bi1[4], bi2[4];
#pragma unroll
    for (int g = 0; g < 4; g++) {
        int j = hh + 256 * g;
        me0[g] = d_Menc[j]; me1[g] = d_Menc[1024 + j];
        bi1[g] = bih[j];    bi2[g] = bhh[j];
    }
    const float gbr_t = gbr[hh];
    const float pbr_t = pbr[hh];
    __syncthreads();

    for (int s = 0; s < S; s++) {
        // ---- gate partials: h_{s-1} @ Whh^T over this thread's K half ----
        float acc[4][4];
#pragma unroll
        for (int g = 0; g < 4; g++)
#pragma unroll
            for (int r = 0; r < 4; r++) acc[g][r] = 0.0f;
#pragma unroll 2
        for (int kg = 0; kg < 32; kg++) {
            int k = k0 + kg * 4;
            float4 xv[4];
#pragma unroll
            for (int r = 0; r < 4; r++) xv[r] = *(const float4*)&hs[r][k];
#pragma unroll
            for (int g = 0; g < 4; g++) {
                float4 w = *(const float4*)&Whh[(size_t)(hh + 256 * g) * 256 + k];
#pragma unroll
                for (int r = 0; r < 4; r++) {
                    acc[g][r] = fmaf(w.x, xv[r].x, acc[g][r]);
                    acc[g][r] = fmaf(w.y, xv[r].y, acc[g][r]);
                    acc[g][r] = fmaf(w.z, xv[r].z, acc[g][r]);
                    acc[g][r] = fmaf(w.w, xv[r].w, acc[g][r]);
                }
            }
        }
        if (half == 1) {
#pragma unroll
            for (int g = 0; g < 4; g++)
#pragma unroll
                for (int r = 0; r < 4; r++) red[g * 4 + r][hh] = acc[g][r];
        }
        __syncthreads();

        if (half == 0) {
#pragma unroll
            for (int r = 0; r < 4; r++) {
                int b = b0 + r;
                float a0 = inputs[((size_t)b * 2 + 0) * S + s];
                float a1 = inputs[((size_t)b * 2 + 1) * S + s];
                float pre[4];
#pragma unroll
                for (int g = 0; g < 4; g++) {
                    float hsum = acc[g][r] + red[g * 4 + r][hh];
                    float xv   = fmaf(a1, me1[g], a0 * me0[g]);
                    pre[g] = hsum + ((xv + bi1[g]) + bi2[g]);
                }
                float ig = sigf(pre[0]);
                float fg = sigf(pre[1]);
                float gg = tanhf(pre[2]);
                float og = sigf(pre[3]);
                float c  = fg * creg[r] + ig * gg;
                creg[r]  = c;
                float h  = og * tanhf(c);
                hs[r][hh] = h;
                d_enc[((size_t)b * S + s) * H + hh] = h;
            }
        }
        __syncthreads();

        // ---- fused ref projections of h_s ----
        float rg[4] = {0.f, 0.f, 0.f, 0.f};
        float rp[4] = {0.f, 0.f, 0.f, 0.f};
#pragma unroll 2
        for (int kg = 0; kg < 32; kg++) {
            int k = k0 + kg * 4;
            float4 wg = *(const float4*)&gWr[(size_t)hh * 256 + k];
            float4 wp = *(const float4*)&pWr[(size_t)hh * 256 + k];
#pragma unroll
            for (int r = 0; r < 4; r++) {
                float4 hv = *(const float4*)&hs[r][k];
                rg[r] = fmaf(wg.x, hv.x, rg[r]); rg[r] = fmaf(wg.y, hv.y, rg[r]);
                rg[r] = fmaf(wg.z, hv.z, rg[r]); rg[r] = fmaf(wg.w, hv.w, rg[r]);
                rp[r] = fmaf(wp.x, hv.x, rp[r]); rp[r] = fmaf(wp.y, hv.y, rp[r]);
                rp[r] = fmaf(wp.z, hv.z, rp[r]); rp[r] = fmaf(wp.w, hv.w, rp[r]);
            }
        }
        if (half == 1) {
#pragma unroll
            for (int r = 0; r < 4; r++) { red[r][hh] = rg[r]; red[4 + r][hh] = rp[r]; }
        }
        __syncthreads();
        if (half == 0) {
#pragma unroll
            for (int r = 0; r < 4; r++) {
                size_t o = ((size_t)(b0 + r) * S + s) * H + hh;
                d_refg[o] = (rg[r] + red[r][hh])     + gbr_t;
                d_refp[o] = (rp[r] + red[4 + r][hh]) + pbr_t;
            }
        }
        __syncthreads();
    }
    if (half == 0) {
#pragma unroll
        for (int r = 0; r < 4; r++) {
            d_h[(size_t)(b0 + r) * H + hh] = hs[r][hh];
            d_c[(size_t)(b0 + r) * H + hh] = creg[r];
        }
    }
}

// ---------------- persistent decoder: 4 rows/block, 512 threads -------------------
__global__ void __launch_bounds__(512)
decoderk(const float* __restrict__ inputs,
         const float* __restrict__ Whh,
         const float* __restrict__ bih, const float* __restrict__ bhh,
         const float* __restrict__ gWq, const float* __restrict__ gbq,
         const float* __restrict__ gV,
         const float* __restrict__ pWq, const float* __restrict__ pbq,
         const float* __restrict__ pV,
         float* __restrict__ out_probs, float* __restrict__ out_idx)
{
    const int tid  = threadIdx.x;
    const int hh   = tid & 255;
    const int half = tid >> 8;
    const int k0   = half * 128;
    const int lane = tid & 31;
    const int w    = tid >> 5;            // 0..15
    const int b0   = blockIdx.x * 4;

    __shared__ __align__(16) float hs[4][256];
    __shared__ __align__(16) float qs[4][256];     // qq, then readout q
    __shared__ __align__(16) float qps[4][256];
    __shared__ __align__(16) float red[16][256];
    __shared__ float lgm[4][100];
    __shared__ float pr [4][100];
    __shared__ float sa0[4], sa1[4];
    __shared__ unsigned char msk[4][104];
    __shared__ int sidx[4];

    float creg[4];

    // hoisted constants
    float md0[4], md1[4], bi1[4], bi2[4];
#pragma unroll
    for (int g = 0; g < 4; g++) {
        int j = hh + 256 * g;
        md0[g] = d_Mdec[j]; md1[g] = d_Mdec[1024 + j];
        bi1[g] = bih[j];    bi2[g] = bhh[j];
    }
    float xst[4];
#pragma unroll
    for (int g = 0; g < 4; g++) xst[g] = d_xstart[hh + 256 * g];
    const float gbq_t = gbq[hh];
    const float pbq_t = pbq[hh];
    // attention V vectors (per-lane hoists)
    float gvv[8], pvv[8];
#pragma unroll
    for (int k = 0; k < 8; k++) { gvv[k] = gV[k * 32 + lane]; pvv[k] = pV[k * 32 + lane]; }

    if (half == 0) {
#pragma unroll
        for (int r = 0; r < 4; r++) {
            hs[r][hh] = d_h[(size_t)(b0 + r) * H + hh];
            creg[r]   = d_c[(size_t)(b0 + r) * H + hh];
        }
    }
    for (int i = tid; i < 4 * 100; i += 512) msk[i / 100][i % 100] = 0;
    __syncthreads();

    for (int t = 0; t < S; t++) {
        // ================= LSTM gates: h @ Whh^T (K-split) + rank-2 input ========
        float acc[4][4];
#pragma unroll
        for (int g = 0; g < 4; g++)
#pragma unroll
            for (int r = 0; r < 4; r++) acc[g][r] = 0.0f;
#pragma unroll 2
        for (int kg = 0; kg < 32; kg++) {
            int k = k0 + kg * 4;
            float4 xv[4];
#pragma unroll
            for (int r = 0; r < 4; r++) xv[r] = *(const float4*)&hs[r][k];
#pragma unroll
            for (int g = 0; g < 4; g++) {
                float4 wv = *(const float4*)&Whh[(size_t)(hh + 256 * g) * 256 + k];
#pragma unroll
                for (int r = 0; r < 4; r++) {
                    acc[g][r] = fmaf(wv.x, xv[r].x, acc[g][r]);
                    acc[g][r] = fmaf(wv.y, xv[r].y, acc[g][r]);
                    acc[g][r] = fmaf(wv.z, xv[r].z, acc[g][r]);
                    acc[g][r] = fmaf(wv.w, xv[r].w, acc[g][r]);
                }
            }
        }
        if (half == 1) {
#pragma unroll
            for (int g = 0; g < 4; g++)
#pragma unroll
                for (int r = 0; r < 4; r++) red[g * 4 + r][hh] = acc[g][r];
        }
        __syncthreads();
        if (half == 0) {
#pragma unroll
            for (int r = 0; r < 4; r++) {
                float pre[4];
#pragma unroll
                for (int g = 0; g < 4; g++) {
                    float hsum = acc[g][r] + red[g * 4 + r][hh];
                    float xv   = (t == 0) ? xst[g]
                               : fmaf(sa1[r], md1[g], sa0[r] * md0[g]);
                    pre[g] = ((hsum + xv) + bi1[g]) + bi2[g];
                }
                float ig = sigf(pre[0]);
                float fg = sigf(pre[1]);
                float gg = tanhf(pre[2]);
                float og = sigf(pre[3]);
                float c  = fg * creg[r] + ig * gg;
                creg[r]  = c;
                hs[r][hh] = og * tanhf(c);
            }
        }
        __syncthreads();

        // ================= qq = h @ gWq^T + gbq (K-split) ========================
        {
            float a[4] = {0.f, 0.f, 0.f, 0.f};
#pragma unroll 2
            for (int kg = 0; kg < 32; kg++) {
                int k = k0 + kg * 4;
                float4 wv = *(const float4*)&gWq[(size_t)hh * 256 + k];
#pragma unroll
                for (int r = 0; r < 4; r++) {
                    float4 hv = *(const float4*)&hs[r][k];
                    a[r] = fmaf(wv.x, hv.x, a[r]); a[r] = fmaf(wv.y, hv.y, a[r]);
                    a[r] = fmaf(wv.z, hv.z, a[r]); a[r] = fmaf(wv.w, hv.w, a[r]);
                }
            }
            if (half == 1) {
#pragma unroll
                for (int r = 0; r < 4; r++) red[r][hh] = a[r];
            }
            __syncthreads();
            if (half == 0) {
#pragma unroll
                for (int r = 0; r < 4; r++) qs[r][hh] = (a[r] + red[r][hh]) + gbq_t;
            }
        }
        __syncthreads();

        // ================= glimpse logits (16 warps: r = w>>2, quarter = w&3) =====
        {
            int r  = w >> 2;
            int s0 = (w & 3) * 25;
            float qv[8];
#pragma unroll
            for (int k = 0; k < 8; k++) qv[k] = qs[r][k * 32 + lane];
#pragma unroll 2
            for (int si = 0; si < 25; si++) {
                int s = s0 + si;
                const float* rp = &d_refg[(((size_t)(b0 + r)) * S + s) * H];
                float sum = 0.0f;
#pragma unroll
                for (int k = 0; k < 8; k++)
                    sum = fmaf(gvv[k], tanhf(qv[k] + __ldg(&rp[k * 32 + lane])), sum);
#pragma unroll
                for (int o = 16; o > 0; o >>= 1) sum += __shfl_xor_sync(0xffffffffu, sum, o);
                if (lane == 0) lgm[r][s] = msk[r][s] ? neg_inf() : sum;
            }
        }
        __syncthreads();

        // ================= glimpse softmax -> pr (bit-identical to R7) ===========
        if (w < 4) {
            int r = w;
            float v[4];
#pragma unroll
            for (int j = 0; j < 4; j++) {
                int s = lane + 32 * j;
                v[j] = (s < 100) ? lgm[r][s] : neg_inf();
            }
            float m = fmaxf(fmaxf(v[0], v[1]), fmaxf(v[2], v[3]));
#pragma unroll
            for (int o = 16; o > 0; o >>= 1) m = fmaxf(m, __shfl_xor_sync(0xffffffffu, m, o));
            float e[4];
#pragma unroll
            for (int j = 0; j < 4; j++) {
                int s = lane + 32 * j;
                e[j] = (s < 100) ? expf(v[j] - m) : 0.0f;
            }
            float sum = (e[0] + e[2]) + (e[1] + e[3]);
#pragma unroll
            for (int o = 16; o > 0; o >>= 1) sum += __shfl_xor_sync(0xffffffffu, sum, o);
#pragma unroll
            for (int j = 0; j < 4; j++) {
                int s = lane + 32 * j;
                if (s < 100) pr[r][s] = e[j] / sum;
            }
        }
        __syncthreads();

        // ================= readout: q = softmax(lg) @ enc (S-split by half) ======
        {
            float a[4] = {0.f, 0.f, 0.f, 0.f};
            int sBase = half * 50;
            for (int si = 0; si < 50; si++) {
                int s = sBase + si;
#pragma unroll
                for (int r = 0; r < 4; r++)
                    a[r] = fmaf(pr[r][s],
                                __ldg(&d_enc[(((size_t)(b0 + r)) * S + s) * H + hh]),
                                a[r]);
            }
            if (half == 1) {
#pragma unroll
                for (int r = 0; r < 4; r++) red[r][hh] = a[r];
            }
            __syncthreads();
            if (half == 0) {
#pragma unroll
                for (int r = 0; r < 4; r++) qs[r][hh] = a[r] + red[r][hh];
            }
        }
        __syncthreads();

        // ================= qp = q @ pWq^T + pbq (K-split) ========================
        {
            float a[4] = {0.f, 0.f, 0.f, 0.f};
#pragma unroll 2
            for (int kg = 0; kg < 32; kg++) {
                int k = k0 + kg * 4;
                float4 wv = *(const float4*)&pWq[(size_t)hh * 256 + k];
#pragma unroll
                for (int r = 0; r < 4; r++) {
                    float4 hv = *(const float4*)&qs[r][k];
                    a[r] = fmaf(wv.x, hv.x, a[r]); a[r] = fmaf(wv.y, hv.y, a[r]);
                    a[r] = fmaf(wv.z, hv.z, a[r]); a[r] = fmaf(wv.w, hv.w, a[r]);
                }
            }
            if (half == 1) {
#pragma unroll
                for (int r = 0; r < 4; r++) red[4 + r][hh] = a[r];
            }
            __syncthreads();
            if (half == 0) {
#pragma unroll
                for (int r = 0; r < 4; r++) qps[r][hh] = (a[r] + red[4 + r][hh]) + pbq_t;
            }
        }
        __syncthreads();

        // ================= pointer logits ========================================
        {
            int r  = w >> 2;
            int s0 = (w & 3) * 25;
            float qv[8];
#pragma unroll
            for (int k = 0; k < 8; k++) qv[k] = qps[r][k * 32 + lane];
#pragma unroll 2
            for (int si = 0; si < 25; si++) {
                int s = s0 + si;
                const float* rp = &d_refp[(((size_t)(b0 + r)) * S + s) * H];
                float sum = 0.0f;
#pragma unroll
                for (int k = 0; k < 8; k++)
                    sum = fmaf(pvv[k], tanhf(qv[k] + __ldg(&rp[k * 32 + lane])), sum);
#pragma unroll
                for (int o = 16; o > 0; o >>= 1) sum += __shfl_xor_sync(0xffffffffu, sum, o);
                if (lane == 0) lgm[r][s] = msk[r][s] ? neg_inf() : (10.0f * tanhf(sum));
            }
        }
        __syncthreads();

        // ================= sample (bit-identical to R7) ==========================
        if (w < 4) {
            int r = w;
            int b = b0 + r;
            float v[4];
#pragma unroll
            for (int j = 0; j < 4; j++) {
                int s = lane + 32 * j;
                v[j] = (s < 100) ? lgm[r][s] : neg_inf();
            }
            float bv = neg_inf(); int bi = 0;
#pragma unroll
            for (int j = 0; j < 4; j++) {
                int s = lane + 32 * j;
                if (s < 100) {
                    float y = v[j] + d_gum[((size_t)t * B + b) * S + s];
                    if (y > bv) { bv = y; bi = s; }
                }
            }
#pragma unroll
            for (int o = 16; o > 0; o >>= 1) {
                float vo = __shfl_xor_sync(0xffffffffu, bv, o);
                int   io = __shfl_xor_sync(0xffffffffu, bi, o);
                if (vo > bv || (vo == bv && io < bi)) { bv = vo; bi = io; }
            }
            float m = fmaxf(fmaxf(v[0], v[1]), fmaxf(v[2], v[3]));
#pragma unroll
            for (int o = 16; o > 0; o >>= 1) m = fmaxf(m, __shfl_xor_sync(0xffffffffu, m, o));
            float e[4];
#pragma unroll
            for (int j = 0; j < 4; j++) {
                int s = lane + 32 * j;
                e[j] = (s < 100) ? expf(v[j] - m) : 0.0f;
            }
            float sum = (e[0] + e[2]) + (e[1] + e[3]);
#pragma unroll
            for (int o = 16; o > 0; o >>= 1) sum += __shfl_xor_sync(0xffffffffu, sum, o);
#pragma unroll
            for (int j = 0; j < 4; j++) {
                int s = lane + 32 * j;
                if (s < 100) out_probs[((size_t)t * B + b) * S + s] = e[j] / sum;
            }
            if (lane == 0) {
                sidx[r] = bi;
                msk[r][bi] = 1;
                out_idx[(size_t)t * B + b] = (float)bi;
                sa0[r] = inputs[((size_t)b * 2 + 0) * S + bi];
                sa1[r] = inputs[((size_t)b * 2 + 1) * S + bi];
            }
        }
        __syncthreads();
    }
}

// ---------------- host ----------------
extern "C" void kernel_launch(void* const* d_in, const int* in_sizes, int n_in,
                              void* d_out, int out_size)
{
    (void)in_sizes; (void)n_in; (void)out_size;
    const float* inputs  = (const float*)d_in[0];
    const float* emb     = (const float*)d_in[1];
    const float* enc_Wih = (const float*)d_in[2];
    const float* enc_Whh = (const float*)d_in[3];
    const float* enc_bih = (const float*)d_in[4];
    const float* enc_bhh = (const float*)d_in[5];
    const float* dec_Wih = (const float*)d_in[6];
    const float* dec_Whh = (const float*)d_in[7];
    const float* dec_bih = (const float*)d_in[8];
    const float* dec_bhh = (const float*)d_in[9];
    const float* g_Wq    = (const float*)d_in[10];
    const float* g_bq    = (const float*)d_in[11];
    const float* g_Wr    = (const float*)d_in[12];
    const float* g_br    = (const float*)d_in[13];
    const float* g_V     = (const float*)d_in[14];
    const float* p_Wq    = (const float*)d_in[15];
    const float* p_bq    = (const float*)d_in[16];
    const float* p_Wr    = (const float*)d_in[17];
    const float* p_br    = (const float*)d_in[18];
    const float* p_V     = (const float*)d_in[19];
    const float* start   = (const float*)d_in[20];

    float* out       = (float*)d_out;
    float* out_probs = out;                              // [S,B,S]
    float* out_idx   = out + (size_t)S * B * S;          // [S,B] (as float)

    gumbelk <<<(S * B * S + 255) / 256, 256>>>();
    precompk<<<4, 256>>>(emb, enc_Wih, dec_Wih, start);

    encoderk<<<B / 4, 512>>>(inputs, enc_Whh, enc_bih, enc_bhh,
                             g_Wr, g_br, p_Wr, p_br);

    decoderk<<<B / 4, 512>>>(inputs, dec_Whh, dec_bih, dec_bhh,
                             g_Wq, g_bq, g_V, p_Wq, p_bq, p_V,
                             out_probs, out_idx);
}